// round 10
// baseline (speedup 1.0000x reference)
#include <cuda_runtime.h>
#include <cstdint>

// Persistent single-kernel MLP: x[N,16] -> L1+BN+ReLU -> L2+BN+ReLU -> L3+BN+ReLU -> L4(->1)
// v6: 256-row tiles, 2 rows/thread (weight-broadcast LDS amortized), 16B cp.async.cg
// double-buffered swizzled staging, float4 BN at read, packed f32x2 FFMA, in-kernel
// grid barriers + BN reduction. Dynamic smem (~73KB), 2 CTAs/SM.

#define EPSV 1e-5f
#define NCTA 296
#define TR 256                  // tile rows
#define TBUF 8448               // floats per buffer: max(staged 256*32=8192, scratch 256*33=8448)

__device__ float g_Z[(size_t)2097152 * 32];
__device__ float g_partial[NCTA * 64];
__device__ float g_bnab[64];                       // a[32], c[32]
__device__ unsigned int g_cnt[4]  = {0, 0, 0, 0};  // monotonic across graph replays
__device__ unsigned int g_flag[4] = {0, 0, 0, 0};

// ---------------- packed f32x2 helpers ----------------
__device__ __forceinline__ unsigned long long pack2(float lo, float hi) {
    unsigned long long r;
    asm("mov.b64 %0, {%1, %2};" : "=l"(r) : "r"(__float_as_uint(lo)), "r"(__float_as_uint(hi)));
    return r;
}
__device__ __forceinline__ void unpack2(unsigned long long v, float& lo, float& hi) {
    unsigned int a, b;
    asm("mov.b64 {%0, %1}, %2;" : "=r"(a), "=r"(b) : "l"(v));
    lo = __uint_as_float(a); hi = __uint_as_float(b);
}
__device__ __forceinline__ unsigned long long splat2(float x) {
    unsigned long long r;
    unsigned int xi = __float_as_uint(x);
    asm("mov.b64 %0, {%1, %1};" : "=l"(r) : "r"(xi));
    return r;
}
__device__ __forceinline__ void fma2(unsigned long long& d, unsigned long long a, unsigned long long b) {
    asm("fma.rn.f32x2 %0, %1, %2, %0;" : "+l"(d) : "l"(a), "l"(b));
}
__device__ __forceinline__ void add2(unsigned long long& d, unsigned long long a) {
    asm("add.rn.f32x2 %0, %0, %1;" : "+l"(d) : "l"(a));
}

// ---------------- async copy + sync helpers ----------------
__device__ __forceinline__ unsigned int smem_u32(const void* p) {
    return (unsigned int)__cvta_generic_to_shared(p);
}
__device__ __forceinline__ void cp16(unsigned int dst, const float4* src) {
    asm volatile("cp.async.cg.shared.global [%0], [%1], 16;" :: "r"(dst), "l"(src));
}
__device__ __forceinline__ void cp_commit() { asm volatile("cp.async.commit_group;" ::: "memory"); }
__device__ __forceinline__ void cp_wait1()  { asm volatile("cp.async.wait_group 1;" ::: "memory"); }
__device__ __forceinline__ void cp_wait0()  { asm volatile("cp.async.wait_group 0;" ::: "memory"); }
__device__ __forceinline__ unsigned int ld_acq(unsigned int* p) {
    unsigned int v;
    asm volatile("ld.acquire.gpu.u32 %0, [%1];" : "=r"(v) : "l"(p));
    return v;
}
__device__ __forceinline__ void st_rel(unsigned int* p, unsigned int v) {
    asm volatile("st.release.gpu.u32 [%0], %1;" :: "l"(p), "r"(v));
}

struct __align__(16) Smem {
    float T[2][TBUF];                    // staging (swizzled f4) + z scratch (stride 33)
    unsigned long long Wp[32 * 16];      // Wp[k*16+jj] = {W[2jj][k], W[2jj+1][k]}
    unsigned long long Bp[16];
    __align__(16) float A[32];           // BN scale of input layer
    __align__(16) float C[32];           // BN shift
    unsigned long long Red[8][16];
    float Stot[64];
    unsigned int ticket;
};

// swizzled float4 index within a staged tile
template<int KIN>
__device__ __forceinline__ int swz(int row, int c) {
    constexpr int C4 = KIN / 4;
    if (KIN == 32) return row * C4 + (c ^ (row & 7));
    else           return row * C4 + ((c + (row >> 1)) & 3);
}

// ---------------- one layer: z = BNReLU(zin) @ W^T + b, stats of z ----------------
template<int KIN, bool BN>
__device__ void run_layer(Smem& sm, const float* __restrict__ zin,
                          const float* __restrict__ W, const float* __restrict__ b,
                          int ntiles, int tid)
{
    constexpr int C4  = KIN / 4;                 // float4 chunks per row
    constexpr int PER = TR * C4 / 256;           // cp.async.16B per thread per tile (8 or 4)

    for (int idx = tid; idx < KIN * 16; idx += 256) {
        int k = idx >> 4, jj = idx & 15;
        sm.Wp[idx] = pack2(W[(2 * jj) * KIN + k], W[(2 * jj + 1) * KIN + k]);
    }
    if (tid < 16) sm.Bp[tid] = pack2(b[2 * tid], b[2 * tid + 1]);
    __syncthreads();

    const int half = tid >> 7;       // feature half: 0 -> feats 0..15, 1 -> 16..31
    const int r    = tid & 127;      // row slot; thread owns rows r and r+128

    unsigned long long vsum[8], vsq[8];
#pragma unroll
    for (int m = 0; m < 8; ++m) { vsum[m] = 0ull; vsq[m] = 0ull; }

    // prologue: prefetch first tile into buffer 0
    const int t0 = blockIdx.x;
    {
        const float4* src = reinterpret_cast<const float4*>(zin + (size_t)t0 * TR * KIN);
        float* dstT = sm.T[0];
#pragma unroll
        for (int j = 0; j < PER; ++j) {
            int i = tid + 256 * j;
            cp16(smem_u32(dstT + swz<KIN>(i / C4, i % C4) * 4), src + i);
        }
        cp_commit();
    }

    int it = 0;
    for (int t = t0; t < ntiles; t += NCTA, ++it) {
        const int cur = it & 1;

        const int tn = t + NCTA;
        if (tn < ntiles) {
            const float4* src = reinterpret_cast<const float4*>(zin + (size_t)tn * TR * KIN);
            float* dstT = sm.T[cur ^ 1];
#pragma unroll
            for (int j = 0; j < PER; ++j) {
                int i = tid + 256 * j;
                cp16(smem_u32(dstT + swz<KIN>(i / C4, i % C4) * 4), src + i);
            }
        }
        cp_commit();
        cp_wait1();
        __syncthreads();

        float* T = sm.T[cur];
        const float4* T4 = reinterpret_cast<const float4*>(T);

        // ---- GEMM: 16 features x 2 rows per thread ----
        unsigned long long z0[8], z1[8];
        const unsigned long long* bp = &sm.Bp[half * 8];
#pragma unroll
        for (int m = 0; m < 8; ++m) { z0[m] = bp[m]; z1[m] = bp[m]; }

#pragma unroll
        for (int c = 0; c < C4; ++c) {
            float4 v0 = T4[swz<KIN>(r, c)];
            float4 v1 = T4[swz<KIN>(r + 128, c)];
            if (BN) {
                float4 A4  = reinterpret_cast<const float4*>(sm.A)[c];
                float4 C4v = reinterpret_cast<const float4*>(sm.C)[c];
                v0.x = fmaxf(fmaf(v0.x, A4.x, C4v.x), 0.0f);
                v0.y = fmaxf(fmaf(v0.y, A4.y, C4v.y), 0.0f);
                v0.z = fmaxf(fmaf(v0.z, A4.z, C4v.z), 0.0f);
                v0.w = fmaxf(fmaf(v0.w, A4.w, C4v.w), 0.0f);
                v1.x = fmaxf(fmaf(v1.x, A4.x, C4v.x), 0.0f);
                v1.y = fmaxf(fmaf(v1.y, A4.y, C4v.y), 0.0f);
                v1.z = fmaxf(fmaf(v1.z, A4.z, C4v.z), 0.0f);
                v1.w = fmaxf(fmaf(v1.w, A4.w, C4v.w), 0.0f);
            }
            const float f0[4] = {v0.x, v0.y, v0.z, v0.w};
            const float f1[4] = {v1.x, v1.y, v1.z, v1.w};
#pragma unroll
            for (int u = 0; u < 4; ++u) {
                int k = c * 4 + u;
                unsigned long long p0 = splat2(f0[u]);
                unsigned long long p1 = splat2(f1[u]);
                const ulonglong2* wp = reinterpret_cast<const ulonglong2*>(&sm.Wp[k * 16 + half * 8]);
                ulonglong2 wa = wp[0], wb = wp[1], wc = wp[2], wd = wp[3];
                fma2(z0[0], p0, wa.x); fma2(z1[0], p1, wa.x);
                fma2(z0[1], p0, wa.y); fma2(z1[1], p1, wa.y);
                fma2(z0[2], p0, wb.x); fma2(z1[2], p1, wb.x);
                fma2(z0[3], p0, wb.y); fma2(z1[3], p1, wb.y);
                fma2(z0[4], p0, wc.x); fma2(z1[4], p1, wc.x);
                fma2(z0[5], p0, wc.y); fma2(z1[5], p1, wc.y);
                fma2(z0[6], p0, wd.x); fma2(z1[6], p1, wd.x);
                fma2(z0[7], p0, wd.y); fma2(z1[7], p1, wd.y);
            }
        }

        // ---- stats (both rows) ----
#pragma unroll
        for (int m = 0; m < 8; ++m) {
            add2(vsum[m], z0[m]); add2(vsum[m], z1[m]);
            fma2(vsq[m], z0[m], z0[m]); fma2(vsq[m], z1[m], z1[m]);
        }
        __syncthreads();                 // all GEMM reads of T done

        // ---- scatter z into T scratch (stride 33, conflict-free scalar STS) ----
#pragma unroll
        for (int m = 0; m < 8; ++m) {
            float f0, f1;
            unpack2(z0[m], f0, f1);
            T[r * 33 + half * 16 + 2 * m]     = f0;
            T[r * 33 + half * 16 + 2 * m + 1] = f1;
            unpack2(z1[m], f0, f1);
            T[(r + 128) * 33 + half * 16 + 2 * m]     = f0;
            T[(r + 128) * 33 + half * 16 + 2 * m + 1] = f1;
        }
        __syncthreads();

        // ---- coalesced z store (2048 float4 per tile) ----
        float4* dst = reinterpret_cast<float4*>(g_Z + (size_t)t * TR * 32);
#pragma unroll
        for (int j = 0; j < 8; ++j) {
            int i = tid + 256 * j;
            int rw = i >> 3, col = (i & 7) * 4;
            const float* s = &T[rw * 33 + col];
            float4 v4; v4.x = s[0]; v4.y = s[1]; v4.z = s[2]; v4.w = s[3];
            dst[i] = v4;
        }
        __syncthreads();                 // scratch free before next prefetch cycle
    }
    cp_wait0();
    __syncthreads();

    // ---- deterministic stat reduction -> per-CTA partials ----
#pragma unroll
    for (int off = 16; off > 0; off >>= 1) {
#pragma unroll
        for (int m = 0; m < 8; ++m) {
            add2(vsum[m], __shfl_xor_sync(0xffffffffu, vsum[m], off));
            add2(vsq[m],  __shfl_xor_sync(0xffffffffu, vsq[m],  off));
        }
    }
    const int w = tid >> 5, lane = tid & 31;
    if (lane == 0) {
#pragma unroll
        for (int m = 0; m < 8; ++m) { sm.Red[w][m] = vsum[m]; sm.Red[w][8 + m] = vsq[m]; }
    }
    __syncthreads();
    if (tid < 64) {
        int s = tid >> 5, j = tid & 31;
        int hh = j >> 4, m = (j & 15) >> 1, hi = j & 1;
        float tot = 0.0f;
        for (int w2 = hh * 4; w2 < hh * 4 + 4; ++w2) {
            float lo, hp; unpack2(sm.Red[w2][s * 8 + m], lo, hp);
            tot += hi ? hp : lo;
        }
        g_partial[blockIdx.x * 64 + tid] = tot;
    }
    __syncthreads();
}

// ---------------- grid barrier + cross-CTA BN coefficient reduction ----------------
__device__ void bn_barrier(Smem& sm, int ph, const float* __restrict__ gamma,
                           const float* __restrict__ beta, float invN, int tid)
{
    __threadfence();
    __syncthreads();
    if (tid == 0) sm.ticket = atomicAdd(&g_cnt[ph], 1);
    __syncthreads();
    const unsigned int ticket = sm.ticket;
    const unsigned int need = ticket - (ticket % NCTA) + NCTA;

    if (ticket % NCTA == NCTA - 1) {
        __threadfence();
        if (tid < 64) {
            float s0 = 0.f, s1 = 0.f;
            for (int c = 0; c < NCTA - 1; c += 2) {
                s0 += g_partial[c * 64 + tid];
                s1 += g_partial[(c + 1) * 64 + tid];
            }
            sm.Stot[tid] = s0 + s1;
        }
        __syncthreads();
        if (tid < 32) {
            float mean = sm.Stot[tid] * invN;
            float var  = sm.Stot[32 + tid] * invN - mean * mean;
            float a = gamma[tid] * rsqrtf(var + EPSV);
            g_bnab[tid]      = a;
            g_bnab[32 + tid] = beta[tid] - mean * a;
        }
        __threadfence();
        __syncthreads();
        if (tid == 0) st_rel(&g_flag[ph], need);
    }
    if (tid == 0) {
        while ((int)(ld_acq(&g_flag[ph]) - need) < 0) __nanosleep(128);
    }
    __syncthreads();
    if (tid < 32) { sm.A[tid] = g_bnab[tid]; sm.C[tid] = g_bnab[32 + tid]; }
    __syncthreads();
}

// ---------------- the persistent kernel ----------------
__global__ void __launch_bounds__(256, 2) mlp_kernel(
    const float* __restrict__ x,
    const float* __restrict__ W1, const float* __restrict__ b1,
    const float* __restrict__ g1, const float* __restrict__ be1,
    const float* __restrict__ W2, const float* __restrict__ b2,
    const float* __restrict__ g2, const float* __restrict__ be2,
    const float* __restrict__ W3, const float* __restrict__ b3,
    const float* __restrict__ g3, const float* __restrict__ be3,
    const float* __restrict__ W4, const float* __restrict__ b4,
    float* __restrict__ out, int ntiles, int nrows, float invN)
{
    extern __shared__ char smem_raw[];
    Smem& sm = *reinterpret_cast<Smem*>(smem_raw);
    const int tid = threadIdx.x;

    run_layer<16, false>(sm, x, W1, b1, ntiles, tid);
    bn_barrier(sm, 0, g1, be1, invN, tid);

    run_layer<32, true>(sm, g_Z, W2, b2, ntiles, tid);
    bn_barrier(sm, 1, g2, be2, invN, tid);

    run_layer<32, true>(sm, g_Z, W3, b3, ntiles, tid);
    bn_barrier(sm, 2, g3, be3, invN, tid);

    // L4: BN3ReLU(z3) . w4 + b4
    if (tid < 32) sm.Stot[tid] = W4[tid];
    __syncthreads();
    const float bb = b4[0];
    for (size_t i = (size_t)blockIdx.x * 256 + tid; i < (size_t)nrows; i += (size_t)NCTA * 256) {
        const float4* zr = reinterpret_cast<const float4*>(g_Z + i * 32);
        float acc = bb;
#pragma unroll
        for (int q = 0; q < 8; ++q) {
            float4 v = zr[q];
            int k = q * 4;
            acc = fmaf(fmaxf(fmaf(v.x, sm.A[k + 0], sm.C[k + 0]), 0.0f), sm.Stot[k + 0], acc);
            acc = fmaf(fmaxf(fmaf(v.y, sm.A[k + 1], sm.C[k + 1]), 0.0f), sm.Stot[k + 1], acc);
            acc = fmaf(fmaxf(fmaf(v.z, sm.A[k + 2], sm.C[k + 2]), 0.0f), sm.Stot[k + 2], acc);
            acc = fmaf(fmaxf(fmaf(v.w, sm.A[k + 3], sm.C[k + 3]), 0.0f), sm.Stot[k + 3], acc);
        }
        out[i] = acc;
    }
}

// ---------------- launcher ----------------
extern "C" void kernel_launch(void* const* d_in, const int* in_sizes, int n_in,
                              void* d_out, int out_size)
{
    const float* x   = (const float*)d_in[0];
    const float* W1  = (const float*)d_in[1];
    const float* b1  = (const float*)d_in[2];
    const float* g1  = (const float*)d_in[3];
    const float* be1 = (const float*)d_in[4];
    const float* W2  = (const float*)d_in[5];
    const float* b2  = (const float*)d_in[6];
    const float* g2  = (const float*)d_in[7];
    const float* be2 = (const float*)d_in[8];
    const float* W3  = (const float*)d_in[9];
    const float* b3  = (const float*)d_in[10];
    const float* g3  = (const float*)d_in[11];
    const float* be3 = (const float*)d_in[12];
    const float* W4  = (const float*)d_in[13];
    const float* b4  = (const float*)d_in[14];

    const int n      = in_sizes[0] / 16;        // 2097152 rows
    const int ntiles = n / TR;                  // 8192
    const float invN = 1.0f / (float)n;

    const int smem_bytes = (int)sizeof(Smem);
    cudaFuncSetAttribute(mlp_kernel, cudaFuncAttributeMaxDynamicSharedMemorySize, smem_bytes);

    mlp_kernel<<<NCTA, 256, smem_bytes>>>(x, W1, b1, g1, be1, W2, b2, g2, be2,
                                          W3, b3, g3, be3, W4, b4,
                                          (float*)d_out, ntiles, n, invN);
}

// round 11
// speedup vs baseline: 1.6317x; 1.6317x over previous
#include <cuda_runtime.h>
#include <cstdint>

// Persistent single-kernel MLP: x[N,16] -> L1+BN+ReLU -> L2+BN+ReLU -> L3+BN+ReLU -> L4(->1)
// v7: v6 (256-row tiles, 2 rows/thread, cp.async.cg double-buffer, swizzled staging)
// with BN statistics moved OUT of the GEMM registers into the store phase
// (4 fixed features/thread = 8 regs instead of 32) to eliminate register spills.

#define EPSV 1e-5f
#define NCTA 296
#define TR 256                  // tile rows
#define TBUF 8448               // floats per buffer: max(staged 256*32=8192, scratch 256*33=8448)

__device__ float g_Z[(size_t)2097152 * 32];
__device__ float g_partial[NCTA * 64];
__device__ float g_bnab[64];                       // a[32], c[32]
__device__ unsigned int g_cnt[4]  = {0, 0, 0, 0};  // monotonic across graph replays
__device__ unsigned int g_flag[4] = {0, 0, 0, 0};

// ---------------- packed f32x2 helpers ----------------
__device__ __forceinline__ unsigned long long pack2(float lo, float hi) {
    unsigned long long r;
    asm("mov.b64 %0, {%1, %2};" : "=l"(r) : "r"(__float_as_uint(lo)), "r"(__float_as_uint(hi)));
    return r;
}
__device__ __forceinline__ void unpack2(unsigned long long v, float& lo, float& hi) {
    unsigned int a, b;
    asm("mov.b64 {%0, %1}, %2;" : "=r"(a), "=r"(b) : "l"(v));
    lo = __uint_as_float(a); hi = __uint_as_float(b);
}
__device__ __forceinline__ unsigned long long splat2(float x) {
    unsigned long long r;
    unsigned int xi = __float_as_uint(x);
    asm("mov.b64 %0, {%1, %1};" : "=l"(r) : "r"(xi));
    return r;
}
__device__ __forceinline__ void fma2(unsigned long long& d, unsigned long long a, unsigned long long b) {
    asm("fma.rn.f32x2 %0, %1, %2, %0;" : "+l"(d) : "l"(a), "l"(b));
}
__device__ __forceinline__ void add2(unsigned long long& d, unsigned long long a) {
    asm("add.rn.f32x2 %0, %0, %1;" : "+l"(d) : "l"(a));
}

// ---------------- async copy + sync helpers ----------------
__device__ __forceinline__ unsigned int smem_u32(const void* p) {
    return (unsigned int)__cvta_generic_to_shared(p);
}
__device__ __forceinline__ void cp16(unsigned int dst, const float4* src) {
    asm volatile("cp.async.cg.shared.global [%0], [%1], 16;" :: "r"(dst), "l"(src));
}
__device__ __forceinline__ void cp_commit() { asm volatile("cp.async.commit_group;" ::: "memory"); }
__device__ __forceinline__ void cp_wait1()  { asm volatile("cp.async.wait_group 1;" ::: "memory"); }
__device__ __forceinline__ void cp_wait0()  { asm volatile("cp.async.wait_group 0;" ::: "memory"); }
__device__ __forceinline__ unsigned int ld_acq(unsigned int* p) {
    unsigned int v;
    asm volatile("ld.acquire.gpu.u32 %0, [%1];" : "=r"(v) : "l"(p));
    return v;
}
__device__ __forceinline__ void st_rel(unsigned int* p, unsigned int v) {
    asm volatile("st.release.gpu.u32 [%0], %1;" :: "l"(p), "r"(v));
}

struct __align__(16) Smem {
    float T[2][TBUF];                    // staging (swizzled f4) + z scratch (stride 33) + stat pass
    unsigned long long Wp[32 * 16];      // Wp[k*16+jj] = {W[2jj][k], W[2jj+1][k]}
    unsigned long long Bp[16];
    __align__(16) float A[32];           // BN scale of input layer
    __align__(16) float C[32];           // BN shift
    float Stot[64];
    unsigned int ticket;
};

// swizzled float4 index within a staged tile
template<int KIN>
__device__ __forceinline__ int swz(int row, int c) {
    constexpr int C4 = KIN / 4;
    if (KIN == 32) return row * C4 + (c ^ (row & 7));
    else           return row * C4 + ((c + (row >> 1)) & 3);
}

// ---------------- one layer: z = BNReLU(zin) @ W^T + b, stats of z ----------------
template<int KIN, bool BN>
__device__ void run_layer(Smem& sm, const float* __restrict__ zin,
                          const float* __restrict__ W, const float* __restrict__ b,
                          int ntiles, int tid)
{
    constexpr int C4  = KIN / 4;                 // float4 chunks per row
    constexpr int PER = TR * C4 / 256;           // cp.async.16B per thread per tile (8 or 4)

    for (int idx = tid; idx < KIN * 16; idx += 256) {
        int k = idx >> 4, jj = idx & 15;
        sm.Wp[idx] = pack2(W[(2 * jj) * KIN + k], W[(2 * jj + 1) * KIN + k]);
    }
    if (tid < 16) sm.Bp[tid] = pack2(b[2 * tid], b[2 * tid + 1]);
    __syncthreads();

    const int half = tid >> 7;       // feature half: 0 -> feats 0..15, 1 -> 16..31
    const int r    = tid & 127;      // row slot; thread owns rows r and r+128

    // store-phase stat accumulators: 4 fixed features (tid&7)*4 .. +3, as 2 f32x2 pairs
    unsigned long long ss01 = 0ull, ss23 = 0ull, qq01 = 0ull, qq23 = 0ull;

    // prologue: prefetch first tile into buffer 0
    const int t0 = blockIdx.x;
    {
        const float4* src = reinterpret_cast<const float4*>(zin + (size_t)t0 * TR * KIN);
        float* dstT = sm.T[0];
#pragma unroll
        for (int j = 0; j < PER; ++j) {
            int i = tid + 256 * j;
            cp16(smem_u32(dstT + swz<KIN>(i / C4, i % C4) * 4), src + i);
        }
        cp_commit();
    }

    int it = 0;
    for (int t = t0; t < ntiles; t += NCTA, ++it) {
        const int cur = it & 1;

        const int tn = t + NCTA;
        if (tn < ntiles) {
            const float4* src = reinterpret_cast<const float4*>(zin + (size_t)tn * TR * KIN);
            float* dstT = sm.T[cur ^ 1];
#pragma unroll
            for (int j = 0; j < PER; ++j) {
                int i = tid + 256 * j;
                cp16(smem_u32(dstT + swz<KIN>(i / C4, i % C4) * 4), src + i);
            }
        }
        cp_commit();
        cp_wait1();
        __syncthreads();

        float* T = sm.T[cur];
        const float4* T4 = reinterpret_cast<const float4*>(T);

        // ---- GEMM: 16 features x 2 rows per thread ----
        unsigned long long z0[8], z1[8];
        const unsigned long long* bp = &sm.Bp[half * 8];
#pragma unroll
        for (int m = 0; m < 8; ++m) { z0[m] = bp[m]; z1[m] = bp[m]; }

#pragma unroll
        for (int c = 0; c < C4; ++c) {
            float4 v0 = T4[swz<KIN>(r, c)];
            float4 v1 = T4[swz<KIN>(r + 128, c)];
            if (BN) {
                float4 A4  = reinterpret_cast<const float4*>(sm.A)[c];
                float4 C4v = reinterpret_cast<const float4*>(sm.C)[c];
                v0.x = fmaxf(fmaf(v0.x, A4.x, C4v.x), 0.0f);
                v0.y = fmaxf(fmaf(v0.y, A4.y, C4v.y), 0.0f);
                v0.z = fmaxf(fmaf(v0.z, A4.z, C4v.z), 0.0f);
                v0.w = fmaxf(fmaf(v0.w, A4.w, C4v.w), 0.0f);
                v1.x = fmaxf(fmaf(v1.x, A4.x, C4v.x), 0.0f);
                v1.y = fmaxf(fmaf(v1.y, A4.y, C4v.y), 0.0f);
                v1.z = fmaxf(fmaf(v1.z, A4.z, C4v.z), 0.0f);
                v1.w = fmaxf(fmaf(v1.w, A4.w, C4v.w), 0.0f);
            }
            const float f0[4] = {v0.x, v0.y, v0.z, v0.w};
            const float f1[4] = {v1.x, v1.y, v1.z, v1.w};
#pragma unroll
            for (int u = 0; u < 4; ++u) {
                int k = c * 4 + u;
                unsigned long long p0 = splat2(f0[u]);
                unsigned long long p1 = splat2(f1[u]);
                const ulonglong2* wp = reinterpret_cast<const ulonglong2*>(&sm.Wp[k * 16 + half * 8]);
                ulonglong2 wa = wp[0], wb = wp[1], wc = wp[2], wd = wp[3];
                fma2(z0[0], p0, wa.x); fma2(z1[0], p1, wa.x);
                fma2(z0[1], p0, wa.y); fma2(z1[1], p1, wa.y);
                fma2(z0[2], p0, wb.x); fma2(z1[2], p1, wb.x);
                fma2(z0[3], p0, wb.y); fma2(z1[3], p1, wb.y);
                fma2(z0[4], p0, wc.x); fma2(z1[4], p1, wc.x);
                fma2(z0[5], p0, wc.y); fma2(z1[5], p1, wc.y);
                fma2(z0[6], p0, wd.x); fma2(z1[6], p1, wd.x);
                fma2(z0[7], p0, wd.y); fma2(z1[7], p1, wd.y);
            }
        }
        __syncthreads();                 // all GEMM reads of T done

        // ---- scatter z into T scratch (stride 33, conflict-free scalar STS) ----
#pragma unroll
        for (int m = 0; m < 8; ++m) {
            float f0, f1;
            unpack2(z0[m], f0, f1);
            T[r * 33 + half * 16 + 2 * m]     = f0;
            T[r * 33 + half * 16 + 2 * m + 1] = f1;
            unpack2(z1[m], f0, f1);
            T[(r + 128) * 33 + half * 16 + 2 * m]     = f0;
            T[(r + 128) * 33 + half * 16 + 2 * m + 1] = f1;
        }
        __syncthreads();

        // ---- coalesced z store + stat accumulation (col fixed per thread) ----
        float4* dst = reinterpret_cast<float4*>(g_Z + (size_t)t * TR * 32);
#pragma unroll
        for (int j = 0; j < 8; ++j) {
            int i = tid + 256 * j;
            int rw = i >> 3, col = (i & 7) * 4;
            const float* s = &T[rw * 33 + col];
            float4 v4; v4.x = s[0]; v4.y = s[1]; v4.z = s[2]; v4.w = s[3];
            dst[i] = v4;
            unsigned long long p01 = pack2(v4.x, v4.y);
            unsigned long long p23 = pack2(v4.z, v4.w);
            add2(ss01, p01); add2(ss23, p23);
            fma2(qq01, p01, p01); fma2(qq23, p23, p23);
        }
        __syncthreads();                 // scratch free before next prefetch cycle
    }
    cp_wait0();
    __syncthreads();

    // ---- deterministic stat reduction -> per-CTA partials ----
    // Thread owns features fb..fb+3 where fb = (tid&7)*4. Regroup through smem.
    {
        float* SS = sm.T[0];             // staging fully consumed; reuse (256 x 8 floats)
        float a0, a1;
        unpack2(ss01, a0, a1); SS[tid * 8 + 0] = a0; SS[tid * 8 + 1] = a1;
        unpack2(ss23, a0, a1); SS[tid * 8 + 2] = a0; SS[tid * 8 + 3] = a1;
        unpack2(qq01, a0, a1); SS[tid * 8 + 4] = a0; SS[tid * 8 + 5] = a1;
        unpack2(qq23, a0, a1); SS[tid * 8 + 6] = a0; SS[tid * 8 + 7] = a1;
        __syncthreads();
        if (tid < 64) {
            const int f = tid & 31, s = tid >> 5;       // feature, stat (0=sum,1=sumsq)
            const int g = f >> 2, u = (f & 3) + s * 4;  // owner group, slot
            float tot = 0.0f;
#pragma unroll
            for (int m = 0; m < 32; ++m) tot += SS[(g + 8 * m) * 8 + u];
            g_partial[blockIdx.x * 64 + tid] = tot;
        }
        __syncthreads();
    }
}

// ---------------- grid barrier + cross-CTA BN coefficient reduction ----------------
__device__ void bn_barrier(Smem& sm, int ph, const float* __restrict__ gamma,
                           const float* __restrict__ beta, float invN, int tid)
{
    __threadfence();
    __syncthreads();
    if (tid == 0) sm.ticket = atomicAdd(&g_cnt[ph], 1);
    __syncthreads();
    const unsigned int ticket = sm.ticket;
    const unsigned int need = ticket - (ticket % NCTA) + NCTA;

    if (ticket % NCTA == NCTA - 1) {
        __threadfence();
        if (tid < 64) {
            float s0 = 0.f, s1 = 0.f;
            for (int c = 0; c < NCTA - 1; c += 2) {
                s0 += g_partial[c * 64 + tid];
                s1 += g_partial[(c + 1) * 64 + tid];
            }
            sm.Stot[tid] = s0 + s1;
        }
        __syncthreads();
        if (tid < 32) {
            float mean = sm.Stot[tid] * invN;
            float var  = sm.Stot[32 + tid] * invN - mean * mean;
            float a = gamma[tid] * rsqrtf(var + EPSV);
            g_bnab[tid]      = a;
            g_bnab[32 + tid] = beta[tid] - mean * a;
        }
        __threadfence();
        __syncthreads();
        if (tid == 0) st_rel(&g_flag[ph], need);
    }
    if (tid == 0) {
        while ((int)(ld_acq(&g_flag[ph]) - need) < 0) __nanosleep(128);
    }
    __syncthreads();
    if (tid < 32) { sm.A[tid] = g_bnab[tid]; sm.C[tid] = g_bnab[32 + tid]; }
    __syncthreads();
}

// ---------------- the persistent kernel ----------------
__global__ void __launch_bounds__(256, 2) mlp_kernel(
    const float* __restrict__ x,
    const float* __restrict__ W1, const float* __restrict__ b1,
    const float* __restrict__ g1, const float* __restrict__ be1,
    const float* __restrict__ W2, const float* __restrict__ b2,
    const float* __restrict__ g2, const float* __restrict__ be2,
    const float* __restrict__ W3, const float* __restrict__ b3,
    const float* __restrict__ g3, const float* __restrict__ be3,
    const float* __restrict__ W4, const float* __restrict__ b4,
    float* __restrict__ out, int ntiles, int nrows, float invN)
{
    extern __shared__ char smem_raw[];
    Smem& sm = *reinterpret_cast<Smem*>(smem_raw);
    const int tid = threadIdx.x;

    run_layer<16, false>(sm, x, W1, b1, ntiles, tid);
    bn_barrier(sm, 0, g1, be1, invN, tid);

    run_layer<32, true>(sm, g_Z, W2, b2, ntiles, tid);
    bn_barrier(sm, 1, g2, be2, invN, tid);

    run_layer<32, true>(sm, g_Z, W3, b3, ntiles, tid);
    bn_barrier(sm, 2, g3, be3, invN, tid);

    // L4: BN3ReLU(z3) . w4 + b4
    if (tid < 32) sm.Stot[tid] = W4[tid];
    __syncthreads();
    const float bb = b4[0];
    for (size_t i = (size_t)blockIdx.x * 256 + tid; i < (size_t)nrows; i += (size_t)NCTA * 256) {
        const float4* zr = reinterpret_cast<const float4*>(g_Z + i * 32);
        float acc = bb;
#pragma unroll
        for (int q = 0; q < 8; ++q) {
            float4 v = zr[q];
            int k = q * 4;
            acc = fmaf(fmaxf(fmaf(v.x, sm.A[k + 0], sm.C[k + 0]), 0.0f), sm.Stot[k + 0], acc);
            acc = fmaf(fmaxf(fmaf(v.y, sm.A[k + 1], sm.C[k + 1]), 0.0f), sm.Stot[k + 1], acc);
            acc = fmaf(fmaxf(fmaf(v.z, sm.A[k + 2], sm.C[k + 2]), 0.0f), sm.Stot[k + 2], acc);
            acc = fmaf(fmaxf(fmaf(v.w, sm.A[k + 3], sm.C[k + 3]), 0.0f), sm.Stot[k + 3], acc);
        }
        out[i] = acc;
    }
}

// ---------------- launcher ----------------
extern "C" void kernel_launch(void* const* d_in, const int* in_sizes, int n_in,
                              void* d_out, int out_size)
{
    const float* x   = (const float*)d_in[0];
    const float* W1  = (const float*)d_in[1];
    const float* b1  = (const float*)d_in[2];
    const float* g1  = (const float*)d_in[3];
    const float* be1 = (const float*)d_in[4];
    const float* W2  = (const float*)d_in[5];
    const float* b2  = (const float*)d_in[6];
    const float* g2  = (const float*)d_in[7];
    const float* be2 = (const float*)d_in[8];
    const float* W3  = (const float*)d_in[9];
    const float* b3  = (const float*)d_in[10];
    const float* g3  = (const float*)d_in[11];
    const float* be3 = (const float*)d_in[12];
    const float* W4  = (const float*)d_in[13];
    const float* b4  = (const float*)d_in[14];

    const int n      = in_sizes[0] / 16;        // 2097152 rows
    const int ntiles = n / TR;                  // 8192
    const float invN = 1.0f / (float)n;

    const int smem_bytes = (int)sizeof(Smem);
    cudaFuncSetAttribute(mlp_kernel, cudaFuncAttributeMaxDynamicSharedMemorySize, smem_bytes);

    mlp_kernel<<<NCTA, 256, smem_bytes>>>(x, W1, b1, g1, be1, W2, b2, g2, be2,
                                          W3, b3, g3, be3, W4, b4,
                                          (float*)d_out, ntiles, n, invN);
}

// round 12
// speedup vs baseline: 1.9913x; 1.2204x over previous
#include <cuda_runtime.h>
#include <cuda_fp16.h>
#include <cstdint>

// Persistent single-kernel MLP: x[N,16] -> L1+BN+ReLU -> L2+BN+ReLU -> L3+BN+ReLU -> L4(->1)
// v8 = v7 (256-row tiles, 2 rows/thread, cp.async double-buffer, store-phase stats)
// with z activations stored in fp16 (half2-packed): halves DRAM traffic and all
// activation-side L1 wavefronts. GEMM math stays fp32 (convert at read).

#define EPSV 1e-5f
#define NCTA 296
#define TR 256                  // tile rows
#define TBUF_U 4352             // uints per buffer: max(staging 256*16B rows=4096u, scratch 256*17=4352u)

__device__ uint4 g_Z16[(size_t)2097152 * 4];       // z as half2: 4 uint4 (32 halfs) per row
__device__ float g_partial[NCTA * 64];
__device__ float g_bnab[64];                       // a[32], c[32]
__device__ unsigned int g_cnt[4]  = {0, 0, 0, 0};  // monotonic across graph replays
__device__ unsigned int g_flag[4] = {0, 0, 0, 0};

// ---------------- packed f32x2 helpers ----------------
__device__ __forceinline__ unsigned long long pack2(float lo, float hi) {
    unsigned long long r;
    asm("mov.b64 %0, {%1, %2};" : "=l"(r) : "r"(__float_as_uint(lo)), "r"(__float_as_uint(hi)));
    return r;
}
__device__ __forceinline__ void unpack2(unsigned long long v, float& lo, float& hi) {
    unsigned int a, b;
    asm("mov.b64 {%0, %1}, %2;" : "=r"(a), "=r"(b) : "l"(v));
    lo = __uint_as_float(a); hi = __uint_as_float(b);
}
__device__ __forceinline__ unsigned long long splat2(float x) {
    unsigned long long r;
    unsigned int xi = __float_as_uint(x);
    asm("mov.b64 %0, {%1, %1};" : "=l"(r) : "r"(xi));
    return r;
}
__device__ __forceinline__ void fma2(unsigned long long& d, unsigned long long a, unsigned long long b) {
    asm("fma.rn.f32x2 %0, %1, %2, %0;" : "+l"(d) : "l"(a), "l"(b));
}
__device__ __forceinline__ void add2(unsigned long long& d, unsigned long long a) {
    asm("add.rn.f32x2 %0, %0, %1;" : "+l"(d) : "l"(a));
}

// ---------------- fp16 pack/unpack ----------------
__device__ __forceinline__ unsigned int f22h2(float lo, float hi) {
    __half2 h = __floats2half2_rn(lo, hi);
    return *reinterpret_cast<unsigned int*>(&h);
}
__device__ __forceinline__ float2 h22f2(unsigned int u) {
    __half2 h = *reinterpret_cast<__half2*>(&u);
    return __half22float2(h);
}

// ---------------- async copy + sync helpers ----------------
__device__ __forceinline__ unsigned int smem_u32(const void* p) {
    return (unsigned int)__cvta_generic_to_shared(p);
}
__device__ __forceinline__ void cp16(unsigned int dst, const void* src) {
    asm volatile("cp.async.cg.shared.global [%0], [%1], 16;" :: "r"(dst), "l"(src));
}
__device__ __forceinline__ void cp_commit() { asm volatile("cp.async.commit_group;" ::: "memory"); }
__device__ __forceinline__ void cp_wait1()  { asm volatile("cp.async.wait_group 1;" ::: "memory"); }
__device__ __forceinline__ void cp_wait0()  { asm volatile("cp.async.wait_group 0;" ::: "memory"); }
__device__ __forceinline__ unsigned int ld_acq(unsigned int* p) {
    unsigned int v;
    asm volatile("ld.acquire.gpu.u32 %0, [%1];" : "=r"(v) : "l"(p));
    return v;
}
__device__ __forceinline__ void st_rel(unsigned int* p, unsigned int v) {
    asm volatile("st.release.gpu.u32 [%0], %1;" :: "l"(p), "r"(v));
}

struct __align__(16) Smem {
    unsigned int Tu[2][TBUF_U];          // staging (swizzled 16B chunks) / z scratch (stride-17 half2)
    unsigned long long Wp[32 * 16];      // Wp[k*16+jj] = {W[2jj][k], W[2jj+1][k]}
    unsigned long long Bp[16];
    __align__(16) float A[32];           // BN scale of input layer
    __align__(16) float C[32];           // BN shift
    float Stot[64];
    unsigned int ticket;
};

// 16B-chunk swizzles (4 chunks per row for both fp32-KIN16 and fp16-KIN32 tiles)
__device__ __forceinline__ int swzF(int row, int c) {  // fp32 x, 16 floats/row
    return row * 4 + ((c + (row >> 1)) & 3);
}
__device__ __forceinline__ int swzH(int row, int c) {  // fp16 z, 16 half2/row
    return row * 4 + (c ^ ((row >> 1) & 3));
}

// ---------------- one layer: z = BNReLU(zin) @ W^T + b  (z stored fp16), stats of z ----------------
template<int KIN, bool BN, bool HALF_IN>
__device__ void run_layer(Smem& sm, const void* __restrict__ zin,
                          const float* __restrict__ W, const float* __restrict__ b,
                          int ntiles, int tid)
{
    for (int idx = tid; idx < KIN * 16; idx += 256) {
        int k = idx >> 4, jj = idx & 15;
        sm.Wp[idx] = pack2(W[(2 * jj) * KIN + k], W[(2 * jj + 1) * KIN + k]);
    }
    if (tid < 16) sm.Bp[tid] = pack2(b[2 * tid], b[2 * tid + 1]);
    __syncthreads();

    const int half = tid >> 7;       // feature half: 0 -> feats 0..15, 1 -> 16..31
    const int r    = tid & 127;      // row slot; thread owns rows r and r+128

    // store-phase stat accumulators: 8 fixed features (tid&3)*8 .. +7
    unsigned long long ss[4], qq[4];
#pragma unroll
    for (int m = 0; m < 4; ++m) { ss[m] = 0ull; qq[m] = 0ull; }

    // tiles are 1024 16B-chunks in gmem for both input types (256 rows x 64B)
    const uint4* gsrc = reinterpret_cast<const uint4*>(zin);

    // prologue: prefetch first tile into buffer 0
    const int t0 = blockIdx.x;
    {
        const uint4* src = gsrc + (size_t)t0 * 1024;
        unsigned int* dstT = sm.Tu[0];
#pragma unroll
        for (int j = 0; j < 4; ++j) {
            int i = tid + 256 * j;
            int row = i >> 2, c = i & 3;
            int sidx = HALF_IN ? swzH(row, c) : swzF(row, c);
            cp16(smem_u32(dstT + sidx * 4), src + i);
        }
        cp_commit();
    }

    int it = 0;
    for (int t = t0; t < ntiles; t += NCTA, ++it) {
        const int cur = it & 1;

        const int tn = t + NCTA;
        if (tn < ntiles) {
            const uint4* src = gsrc + (size_t)tn * 1024;
            unsigned int* dstT = sm.Tu[cur ^ 1];
#pragma unroll
            for (int j = 0; j < 4; ++j) {
                int i = tid + 256 * j;
                int row = i >> 2, c = i & 3;
                int sidx = HALF_IN ? swzH(row, c) : swzF(row, c);
                cp16(smem_u32(dstT + sidx * 4), src + i);
            }
        }
        cp_commit();
        cp_wait1();
        __syncthreads();

        unsigned int* T = sm.Tu[cur];

        // ---- GEMM: 16 features x 2 rows per thread ----
        unsigned long long z0[8], z1[8];
        const unsigned long long* bp = &sm.Bp[half * 8];
#pragma unroll
        for (int m = 0; m < 8; ++m) { z0[m] = bp[m]; z1[m] = bp[m]; }

        if (HALF_IN) {
            const uint4* T4 = reinterpret_cast<const uint4*>(T);
#pragma unroll
            for (int c = 0; c < 4; ++c) {
                uint4 h0 = T4[swzH(r, c)];
                uint4 h1 = T4[swzH(r + 128, c)];
                const unsigned int u0[4] = {h0.x, h0.y, h0.z, h0.w};
                const unsigned int u1[4] = {h1.x, h1.y, h1.z, h1.w};
#pragma unroll
                for (int tq = 0; tq < 4; ++tq) {
                    float2 f0 = h22f2(u0[tq]);
                    float2 f1 = h22f2(u1[tq]);
                    if (BN) {
                        float2 a2 = reinterpret_cast<const float2*>(sm.A)[c * 4 + tq];
                        float2 c2 = reinterpret_cast<const float2*>(sm.C)[c * 4 + tq];
                        f0.x = fmaxf(fmaf(f0.x, a2.x, c2.x), 0.0f);
                        f0.y = fmaxf(fmaf(f0.y, a2.y, c2.y), 0.0f);
                        f1.x = fmaxf(fmaf(f1.x, a2.x, c2.x), 0.0f);
                        f1.y = fmaxf(fmaf(f1.y, a2.y, c2.y), 0.0f);
                    }
                    const float v0[2] = {f0.x, f0.y};
                    const float v1[2] = {f1.x, f1.y};
#pragma unroll
                    for (int e = 0; e < 2; ++e) {
                        int k = c * 8 + tq * 2 + e;
                        unsigned long long p0 = splat2(v0[e]);
                        unsigned long long p1 = splat2(v1[e]);
                        const ulonglong2* wp = reinterpret_cast<const ulonglong2*>(&sm.Wp[k * 16 + half * 8]);
                        ulonglong2 wa = wp[0], wb = wp[1], wc = wp[2], wd = wp[3];
                        fma2(z0[0], p0, wa.x); fma2(z1[0], p1, wa.x);
                        fma2(z0[1], p0, wa.y); fma2(z1[1], p1, wa.y);
                        fma2(z0[2], p0, wb.x); fma2(z1[2], p1, wb.x);
                        fma2(z0[3], p0, wb.y); fma2(z1[3], p1, wb.y);
                        fma2(z0[4], p0, wc.x); fma2(z1[4], p1, wc.x);
                        fma2(z0[5], p0, wc.y); fma2(z1[5], p1, wc.y);
                        fma2(z0[6], p0, wd.x); fma2(z1[6], p1, wd.x);
                        fma2(z0[7], p0, wd.y); fma2(z1[7], p1, wd.y);
                    }
                }
            }
        } else {
            const float4* T4 = reinterpret_cast<const float4*>(T);
#pragma unroll
            for (int c = 0; c < 4; ++c) {
                float4 v0 = T4[swzF(r, c)];
                float4 v1 = T4[swzF(r + 128, c)];
                const float f0[4] = {v0.x, v0.y, v0.z, v0.w};
                const float f1[4] = {v1.x, v1.y, v1.z, v1.w};
#pragma unroll
                for (int u = 0; u < 4; ++u) {
                    int k = c * 4 + u;
                    unsigned long long p0 = splat2(f0[u]);
                    unsigned long long p1 = splat2(f1[u]);
                    const ulonglong2* wp = reinterpret_cast<const ulonglong2*>(&sm.Wp[k * 16 + half * 8]);
                    ulonglong2 wa = wp[0], wb = wp[1], wc = wp[2], wd = wp[3];
                    fma2(z0[0], p0, wa.x); fma2(z1[0], p1, wa.x);
                    fma2(z0[1], p0, wa.y); fma2(z1[1], p1, wa.y);
                    fma2(z0[2], p0, wb.x); fma2(z1[2], p1, wb.x);
                    fma2(z0[3], p0, wb.y); fma2(z1[3], p1, wb.y);
                    fma2(z0[4], p0, wc.x); fma2(z1[4], p1, wc.x);
                    fma2(z0[5], p0, wc.y); fma2(z1[5], p1, wc.y);
                    fma2(z0[6], p0, wd.x); fma2(z1[6], p1, wd.x);
                    fma2(z0[7], p0, wd.y); fma2(z1[7], p1, wd.y);
                }
            }
        }
        __syncthreads();                 // all GEMM reads of T done

        // ---- scatter z as half2 into scratch (stride-17 uints, conflict-free) ----
#pragma unroll
        for (int m = 0; m < 8; ++m) {
            float f0, f1;
            unpack2(z0[m], f0, f1);
            T[r * 17 + half * 8 + m] = f22h2(f0, f1);
            unpack2(z1[m], f0, f1);
            T[(r + 128) * 17 + half * 8 + m] = f22h2(f0, f1);
        }
        __syncthreads();

        // ---- coalesced fp16 z store + stat accumulation (features fixed per thread) ----
        uint4* dst = g_Z16 + (size_t)t * 1024;
#pragma unroll
        for (int j = 0; j < 4; ++j) {
            int i = tid + 256 * j;
            int row = i >> 2, q = i & 3;                  // q = tid & 3 (fixed)
            const unsigned int* s = &T[row * 17 + q * 4];
            unsigned int w0 = s[0], w1 = s[1], w2 = s[2], w3 = s[3];
            uint4 v4; v4.x = w0; v4.y = w1; v4.z = w2; v4.w = w3;
            dst[i] = v4;
            const unsigned int ww[4] = {w0, w1, w2, w3};
#pragma unroll
            for (int m = 0; m < 4; ++m) {
                float2 f = h22f2(ww[m]);
                unsigned long long p = pack2(f.x, f.y);
                add2(ss[m], p);
                fma2(qq[m], p, p);
            }
        }
        __syncthreads();                 // scratch free before next prefetch cycle
    }
    cp_wait0();
    __syncthreads();

    // ---- deterministic stat reduction -> per-CTA partials ----
    // Thread owns features fb..fb+7 where fb = (tid&3)*8. Regroup through smem.
    {
        float* SS = reinterpret_cast<float*>(sm.Tu[0]);   // 4096 floats, staging dead
#pragma unroll
        for (int m = 0; m < 4; ++m) {
            float a0, a1;
            unpack2(ss[m], a0, a1);
            SS[tid * 16 + 2 * m]     = a0;
            SS[tid * 16 + 2 * m + 1] = a1;
            unpack2(qq[m], a0, a1);
            SS[tid * 16 + 8 + 2 * m]     = a0;
            SS[tid * 16 + 8 + 2 * m + 1] = a1;
        }
        __syncthreads();
        if (tid < 64) {
            const int f = tid & 31, s = tid >> 5;        // feature, stat (0=sum,1=sumsq)
            const int g = f >> 3, u = (f & 7) + s * 8;   // owner group (tid&3), slot
            float tot = 0.0f;
#pragma unroll
            for (int m = 0; m < 64; ++m) tot += SS[(g + 4 * m) * 16 + u];
            g_partial[blockIdx.x * 64 + tid] = tot;
        }
        __syncthreads();
    }
}

// ---------------- grid barrier + cross-CTA BN coefficient reduction ----------------
__device__ void bn_barrier(Smem& sm, int ph, const float* __restrict__ gamma,
                           const float* __restrict__ beta, float invN, int tid)
{
    __threadfence();
    __syncthreads();
    if (tid == 0) sm.ticket = atomicAdd(&g_cnt[ph], 1);
    __syncthreads();
    const unsigned int ticket = sm.ticket;
    const unsigned int need = ticket - (ticket % NCTA) + NCTA;

    if (ticket % NCTA == NCTA - 1) {
        __threadfence();
        if (tid < 64) {
            float s0 = 0.f, s1 = 0.f;
            for (int c = 0; c < NCTA - 1; c += 2) {
                s0 += g_partial[c * 64 + tid];
                s1 += g_partial[(c + 1) * 64 + tid];
            }
            sm.Stot[tid] = s0 + s1;
        }
        __syncthreads();
        if (tid < 32) {
            float mean = sm.Stot[tid] * invN;
            float var  = sm.Stot[32 + tid] * invN - mean * mean;
            float a = gamma[tid] * rsqrtf(var + EPSV);
            g_bnab[tid]      = a;
            g_bnab[32 + tid] = beta[tid] - mean * a;
        }
        __threadfence();
        __syncthreads();
        if (tid == 0) st_rel(&g_flag[ph], need);
    }
    if (tid == 0) {
        while ((int)(ld_acq(&g_flag[ph]) - need) < 0) __nanosleep(128);
    }
    __syncthreads();
    if (tid < 32) { sm.A[tid] = g_bnab[tid]; sm.C[tid] = g_bnab[32 + tid]; }
    __syncthreads();
}

// ---------------- the persistent kernel ----------------
__global__ void __launch_bounds__(256, 2) mlp_kernel(
    const float* __restrict__ x,
    const float* __restrict__ W1, const float* __restrict__ b1,
    const float* __restrict__ g1, const float* __restrict__ be1,
    const float* __restrict__ W2, const float* __restrict__ b2,
    const float* __restrict__ g2, const float* __restrict__ be2,
    const float* __restrict__ W3, const float* __restrict__ b3,
    const float* __restrict__ g3, const float* __restrict__ be3,
    const float* __restrict__ W4, const float* __restrict__ b4,
    float* __restrict__ out, int ntiles, int nrows, float invN)
{
    extern __shared__ char smem_raw[];
    Smem& sm = *reinterpret_cast<Smem*>(smem_raw);
    const int tid = threadIdx.x;

    run_layer<16, false, false>(sm, x, W1, b1, ntiles, tid);
    bn_barrier(sm, 0, g1, be1, invN, tid);

    run_layer<32, true, true>(sm, g_Z16, W2, b2, ntiles, tid);
    bn_barrier(sm, 1, g2, be2, invN, tid);

    run_layer<32, true, true>(sm, g_Z16, W3, b3, ntiles, tid);
    bn_barrier(sm, 2, g3, be3, invN, tid);

    // L4: BN3ReLU(z3) . w4 + b4
    if (tid < 32) sm.Stot[tid] = W4[tid];
    __syncthreads();
    const float bb = b4[0];
    for (size_t i = (size_t)blockIdx.x * 256 + tid; i < (size_t)nrows; i += (size_t)NCTA * 256) {
        const uint4* zr = g_Z16 + i * 4;
        float acc = bb;
#pragma unroll
        for (int q = 0; q < 4; ++q) {
            uint4 hv = zr[q];
            const unsigned int hu[4] = {hv.x, hv.y, hv.z, hv.w};
#pragma unroll
            for (int m = 0; m < 4; ++m) {
                int k = q * 8 + m * 2;
                float2 f = h22f2(hu[m]);
                acc = fmaf(fmaxf(fmaf(f.x, sm.A[k],     sm.C[k]),     0.0f), sm.Stot[k],     acc);
                acc = fmaf(fmaxf(fmaf(f.y, sm.A[k + 1], sm.C[k + 1]), 0.0f), sm.Stot[k + 1], acc);
            }
        }
        out[i] = acc;
    }
}

// ---------------- launcher ----------------
extern "C" void kernel_launch(void* const* d_in, const int* in_sizes, int n_in,
                              void* d_out, int out_size)
{
    const float* x   = (const float*)d_in[0];
    const float* W1  = (const float*)d_in[1];
    const float* b1  = (const float*)d_in[2];
    const float* g1  = (const float*)d_in[3];
    const float* be1 = (const float*)d_in[4];
    const float* W2  = (const float*)d_in[5];
    const float* b2  = (const float*)d_in[6];
    const float* g2  = (const float*)d_in[7];
    const float* be2 = (const float*)d_in[8];
    const float* W3  = (const float*)d_in[9];
    const float* b3  = (const float*)d_in[10];
    const float* g3  = (const float*)d_in[11];
    const float* be3 = (const float*)d_in[12];
    const float* W4  = (const float*)d_in[13];
    const float* b4  = (const float*)d_in[14];

    const int n      = in_sizes[0] / 16;        // 2097152 rows
    const int ntiles = n / TR;                  // 8192
    const float invN = 1.0f / (float)n;

    const int smem_bytes = (int)sizeof(Smem);
    cudaFuncSetAttribute(mlp_kernel, cudaFuncAttributeMaxDynamicSharedMemorySize, smem_bytes);

    mlp_kernel<<<NCTA, 256, smem_bytes>>>(x, W1, b1, g1, be1, W2, b2, g2, be2,
                                          W3, b3, g3, be3, W4, b4,
                                          (float*)d_out, ntiles, n, invN);
}